// round 3
// baseline (speedup 1.0000x reference)
#include <cuda_runtime.h>
#include <cuda_bf16.h>
#include <math.h>

// Shapes
// x:      [8,128,64,64]
// off_w:  [27,128,3,3]
// off_b:  [27]
// w:      [128,128,3,3]
// b:      [128]
// gamma:  [128], beta: [128]
// out:    [8,128,64,64] fp32

#define NB   8
#define NC   128
#define NH   64
#define NW   64
#define NHW  4096
#define NKT  9
#define NOFF 27
#define KDIM 1152   // 128*9

// Scratch (static device allocations — allowed)
static __device__ float g_om[NB * NOFF * NHW];        // offset-conv output
static __device__ float g_wT[NKT * NC * NC];          // w transposed to [k][c][o]
static __device__ float g_y[NB * NC * NHW];           // pre-BN conv output
static __device__ float g_stats[2 * NC];              // per-channel sum, sumsq

// ---------------------------------------------------------------------------
// Kernel Z: zero stats + transpose main-conv weights to [kt][c][o] layout so
// GEMM chunk loads are fully coalesced (original stride-9-float reads waste
// 8x L2 sectors).
// ---------------------------------------------------------------------------
__global__ void prep_kernel(const float* __restrict__ w) {
    if (blockIdx.x == 0 && threadIdx.x < 2 * NC) g_stats[threadIdx.x] = 0.0f;
    int n = NKT * NC * NC;  // 147456
    for (int i = blockIdx.x * blockDim.x + threadIdx.x; i < n;
         i += gridDim.x * blockDim.x) {
        int o  = i / KDIM;
        int r  = i % KDIM;
        int c  = r / NKT;
        int kt = r % NKT;
        g_wT[(kt * NC + c) * NC + o] = w[i];
    }
}

// ---------------------------------------------------------------------------
// Kernel A: offset conv  om = conv3x3(x, off_w) + off_b   -> g_om
// Block: 16x16 spatial tile of one batch. 256 threads:
//   slot = tid&127 -> (row lr in 0..7, col lc in 0..15), each thread handles
//   pixels (lr, lr+8); og = tid>>7 splits 27 outputs into 14+13.
// Per channel per thread: 18 x-LDS, 126 w-LDS, 252 FFMA (weight reuse x2).
// ---------------------------------------------------------------------------
__global__ __launch_bounds__(256) void off_conv_kernel(
    const float* __restrict__ x,
    const float* __restrict__ ow,
    const float* __restrict__ ob) {
    __shared__ float xt[18][18];
    __shared__ float wsm[243];

    const int tid  = threadIdx.x;
    const int slot = tid & 127;
    const int og   = tid >> 7;        // 0 or 1
    const int lr   = slot >> 4;       // 0..7
    const int lc   = slot & 15;       // 0..15
    const int b    = blockIdx.z;
    const int by   = blockIdx.y;
    const int bx   = blockIdx.x;

    float acc0[14], acc1[14];
#pragma unroll
    for (int j = 0; j < 14; ++j) { acc0[j] = 0.0f; acc1[j] = 0.0f; }

    for (int ci = 0; ci < NC; ++ci) {
        __syncthreads();
        // load 18x18 halo tile for this channel
        for (int i = tid; i < 324; i += 256) {
            int r = i / 18, c = i % 18;
            int gy = by * 16 + r - 1;
            int gx = bx * 16 + c - 1;
            float v = 0.0f;
            if (gy >= 0 && gy < NH && gx >= 0 && gx < NW)
                v = x[((size_t)(b * NC + ci) << 12) + (gy << 6) + gx];
            xt[r][c] = v;
        }
        // load 27x9 weights for this input channel
        if (tid < 243) {
            int o = tid / 9, t = tid % 9;
            wsm[tid] = ow[((size_t)o * NC + ci) * 9 + t];
        }
        __syncthreads();

        float xv0[9], xv1[9];
#pragma unroll
        for (int dy = 0; dy < 3; ++dy)
#pragma unroll
            for (int dx = 0; dx < 3; ++dx) {
                xv0[dy * 3 + dx] = xt[lr + dy][lc + dx];
                xv1[dy * 3 + dx] = xt[lr + 8 + dy][lc + dx];
            }
#pragma unroll
        for (int j = 0; j < 14; ++j) {
            int o = og * 14 + j;
            if (o < NOFF) {
#pragma unroll
                for (int t = 0; t < 9; ++t) {
                    float wv = wsm[o * 9 + t];
                    acc0[j] = fmaf(xv0[t], wv, acc0[j]);
                    acc1[j] = fmaf(xv1[t], wv, acc1[j]);
                }
            }
        }
    }

    const int gy0 = by * 16 + lr;
    const int gx  = bx * 16 + lc;
#pragma unroll
    for (int j = 0; j < 14; ++j) {
        int o = og * 14 + j;
        if (o < NOFF) {
            float bb = ob[o];
            g_om[((size_t)(b * NOFF + o) << 12) + (gy0 << 6) + gx]       = acc0[j] + bb;
            g_om[((size_t)(b * NOFF + o) << 12) + ((gy0 + 8) << 6) + gx] = acc1[j] + bb;
        }
    }
}

// ---------------------------------------------------------------------------
// Kernel B: fused deformable sampling + implicit GEMM + BN partial stats.
// Block = 128 consecutive pixels (2 image rows of one batch) x all 128 out ch.
// Phase 1: per (pixel, tap) compute bilinear corner weights (mask- and
//          validity-premultiplied) + packed clamped corner coords into SMEM.
// Phase 2: K-loop over 72 chunks (16 input ch x 1 tap). Chunk: load W tile
//          (coalesced from g_wT), compute A tile by gathering x (L1-resident
//          16KB channel planes), then 8x8 register-tile GEMM.
// Epilogue: +bias, store y, per-channel sum/sumsq -> global atomics.
// ---------------------------------------------------------------------------
__global__ __launch_bounds__(256, 2) void dcn_main_kernel(
    const float* __restrict__ x,
    const float* __restrict__ bias) {
    __shared__ float s_w00[NKT][128];
    __shared__ float s_w01[NKT][128];
    __shared__ float s_w10[NKT][128];
    __shared__ float s_w11[NKT][128];
    __shared__ unsigned s_cc[NKT][128];
    __shared__ float s_A[16][128];
    __shared__ float s_W[16][128];
    __shared__ float s_sum[NC];
    __shared__ float s_ssq[NC];

    const int tid     = threadIdx.x;
    const int m0      = blockIdx.x * 128;
    const int b       = m0 >> 12;
    const int rowbase = m0 & 4095;
    const int h0      = rowbase >> 6;

    if (tid < NC) { s_sum[tid] = 0.0f; s_ssq[tid] = 0.0f; }

    // -------- phase 1: sampling metadata --------
    for (int idx = tid; idx < NKT * 128; idx += 256) {
        int kt = idx >> 7;
        int px = idx & 127;
        int h  = h0 + (px >> 6);
        int w  = px & 63;
        const float* omb = g_om + (size_t)b * NOFF * NHW;
        float offy = omb[(2 * kt) * NHW + (h << 6) + w];
        float offx = omb[(2 * kt + 1) * NHW + (h << 6) + w];
        float mv   = omb[(18 + kt) * NHW + (h << 6) + w];
        float msk  = 1.0f / (1.0f + expf(-mv));

        float py  = offy + (float)(h - 1 + kt / 3);
        float pxf = offx + (float)(w - 1 + kt % 3);
        float fy = floorf(py), fx = floorf(pxf);
        float ly = py - fy,    lx = pxf - fx;
        int y0 = (int)fy, x0 = (int)fx;
        int y1 = y0 + 1,  x1 = x0 + 1;
        float vy0 = (y0 >= 0 && y0 < NH) ? 1.0f : 0.0f;
        float vy1 = (y1 >= 0 && y1 < NH) ? 1.0f : 0.0f;
        float vx0 = (x0 >= 0 && x0 < NW) ? 1.0f : 0.0f;
        float vx1 = (x1 >= 0 && x1 < NW) ? 1.0f : 0.0f;

        s_w00[kt][px] = (1.0f - ly) * (1.0f - lx) * msk * vy0 * vx0;
        s_w01[kt][px] = (1.0f - ly) * lx          * msk * vy0 * vx1;
        s_w10[kt][px] = ly          * (1.0f - lx) * msk * vy1 * vx0;
        s_w11[kt][px] = ly          * lx          * msk * vy1 * vx1;

        int y0c = min(max(y0, 0), NH - 1), x0c = min(max(x0, 0), NW - 1);
        int y1c = min(max(y1, 0), NH - 1), x1c = min(max(x1, 0), NW - 1);
        s_cc[kt][px] =
            (unsigned)(y0c | (x0c << 6) | (y1c << 12) | (x1c << 18));
    }

    float acc[64];
#pragma unroll
    for (int i = 0; i < 64; ++i) acc[i] = 0.0f;

    const int p0 = (tid >> 4) << 3;  // pixel sub-tile base
    const int o0 = (tid & 15) << 3;  // out-channel sub-tile base

    // -------- phase 2: K loop (channel-block outer, tap inner for L1 reuse) --
    for (int cb = 0; cb < 8; ++cb) {
        const int c0 = cb << 4;
        for (int kt = 0; kt < NKT; ++kt) {
            __syncthreads();  // previous GEMM done reading s_A/s_W
            // load weight tile [16c][128o] (coalesced)
#pragma unroll
            for (int r = 0; r < 8; ++r) {
                int e  = tid + (r << 8);
                int ci = e >> 7;
                int o  = e & 127;
                s_W[ci][o] = g_wT[((kt << 7) + c0 + ci) * NC + o];
            }
            // compute A tile [16c][128px] by bilinear gather
#pragma unroll
            for (int r = 0; r < 8; ++r) {
                int e  = tid + (r << 8);
                int ci = e >> 7;
                int px = e & 127;
                const float* bp = x + ((size_t)(b * NC + c0 + ci) << 12);
                unsigned cc = s_cc[kt][px];
                int y0c = cc & 63;
                int x0c = (cc >> 6) & 63;
                int y1c = (cc >> 12) & 63;
                int x1c = (cc >> 18) & 63;
                float a = s_w00[kt][px] * __ldg(bp + (y0c << 6) + x0c)
                        + s_w01[kt][px] * __ldg(bp + (y0c << 6) + x1c)
                        + s_w10[kt][px] * __ldg(bp + (y1c << 6) + x0c)
                        + s_w11[kt][px] * __ldg(bp + (y1c << 6) + x1c);
                s_A[ci][px] = a;
            }
            __syncthreads();
            // 8x8 register-tile GEMM update
#pragma unroll
            for (int ci = 0; ci < 16; ++ci) {
                float4 a0 = *(const float4*)(&s_A[ci][p0]);
                float4 a1 = *(const float4*)(&s_A[ci][p0 + 4]);
                float4 w0 = *(const float4*)(&s_W[ci][o0]);
                float4 w1 = *(const float4*)(&s_W[ci][o0 + 4]);
                float av[8] = {a0.x, a0.y, a0.z, a0.w, a1.x, a1.y, a1.z, a1.w};
                float wv[8] = {w0.x, w0.y, w0.z, w0.w, w1.x, w1.y, w1.z, w1.w};
#pragma unroll
                for (int i = 0; i < 8; ++i)
#pragma unroll
                    for (int j = 0; j < 8; ++j)
                        acc[i * 8 + j] = fmaf(av[i], wv[j], acc[i * 8 + j]);
            }
        }
    }

    // -------- epilogue: bias, store y, BN partial stats --------
#pragma unroll
    for (int j = 0; j < 8; ++j) {
        int o = o0 + j;
        float bo = __ldg(bias + o);
        float v[8];
        float s = 0.0f, sq = 0.0f;
#pragma unroll
        for (int i = 0; i < 8; ++i) {
            v[i] = acc[i * 8 + j] + bo;
            s += v[i];
            sq = fmaf(v[i], v[i], sq);
        }
        float* yp = g_y + ((size_t)(b * NC + o) << 12) + rowbase + p0;
        *(float4*)yp       = make_float4(v[0], v[1], v[2], v[3]);
        *(float4*)(yp + 4) = make_float4(v[4], v[5], v[6], v[7]);
        atomicAdd(&s_sum[o], s);
        atomicAdd(&s_ssq[o], sq);
    }
    __syncthreads();
    if (tid < NC) {
        atomicAdd(&g_stats[tid], s_sum[tid]);
        atomicAdd(&g_stats[NC + tid], s_ssq[tid]);
    }
}

// ---------------------------------------------------------------------------
// Kernel D: BatchNorm (batch stats) + ReLU -> d_out
// ---------------------------------------------------------------------------
__global__ __launch_bounds__(256) void bn_relu_kernel(
    float* __restrict__ out,
    const float* __restrict__ gamma,
    const float* __restrict__ beta) {
    int idx = blockIdx.x * 256 + threadIdx.x;  // float4 index, total 1048576
    int o = (idx >> 10) & 127;                 // 1024 float4 per (b,o) plane
    const float invN = 1.0f / 32768.0f;
    float mean = g_stats[o] * invN;
    float var  = g_stats[NC + o] * invN - mean * mean;
    float inv  = rsqrtf(var + 1e-5f);
    float sc   = gamma[o] * inv;
    float sh   = beta[o] - mean * sc;
    float4 v = ((const float4*)g_y)[idx];
    v.x = fmaxf(fmaf(v.x, sc, sh), 0.0f);
    v.y = fmaxf(fmaf(v.y, sc, sh), 0.0f);
    v.z = fmaxf(fmaf(v.z, sc, sh), 0.0f);
    v.w = fmaxf(fmaf(v.w, sc, sh), 0.0f);
    ((float4*)out)[idx] = v;
}

// ---------------------------------------------------------------------------
extern "C" void kernel_launch(void* const* d_in, const int* in_sizes, int n_in,
                              void* d_out, int out_size) {
    const float* x     = (const float*)d_in[0];
    const float* off_w = (const float*)d_in[1];
    const float* off_b = (const float*)d_in[2];
    const float* w     = (const float*)d_in[3];
    const float* bias  = (const float*)d_in[4];
    const float* gamma = (const float*)d_in[5];
    const float* beta  = (const float*)d_in[6];
    float* out = (float*)d_out;

    prep_kernel<<<144, 256>>>(w);
    off_conv_kernel<<<dim3(4, 4, 8), 256>>>(x, off_w, off_b);
    dcn_main_kernel<<<256, 256>>>(x, bias);
    bn_relu_kernel<<<4096, 256>>>(out, gamma, beta);
}